// round 5
// baseline (speedup 1.0000x reference)
#include <cuda_runtime.h>
#include <cstdint>

#define N_NODES 50000
#define N_EDGES 500000
#define D_NODE  128
#define D_HID   256
#define D_OUT   64

// Scratch: P[n][0:256] = nf[n] @ W1[0:128,:],  P[n][256:512] = nf[n] @ W1[128:256,:]
// 50000 * 512 * 4B = 102.4 MB (mostly L2-resident for the gather phase)
__device__ float g_P[N_NODES * 512];

// ---------------- packed f32x2 helpers (exact fp32, 2x FMA throughput) ----------------
__device__ __forceinline__ unsigned long long pack2(float lo, float hi) {
    unsigned long long r;
    asm("mov.b64 %0, {%1, %2};" : "=l"(r) : "r"(__float_as_uint(lo)), "r"(__float_as_uint(hi)));
    return r;
}
__device__ __forceinline__ void fma2(unsigned long long& acc, unsigned long long a, unsigned long long b) {
    asm("fma.rn.f32x2 %0, %1, %2, %0;" : "+l"(acc) : "l"(a), "l"(b));
}
__device__ __forceinline__ float2 unpack2(unsigned long long v) {
    unsigned int lo, hi;
    asm("mov.b64 {%0, %1}, %2;" : "=r"(lo), "=r"(hi) : "l"(v));
    return make_float2(__uint_as_float(lo), __uint_as_float(hi));
}

// =====================================================================================
// Kernel 1: node projection  P = nf @ [W1a | W1b]   (M=50000, K=128, N=512)
// Block: 256 threads, tile 64 nodes x 128 cols. smem: A 32KB + B 64KB = 96KB.
// Thread tile: 8 nodes x 4 cols, accumulators packed in node-pairs.
// =====================================================================================
#define K1_SMEM ((64 * 128 + 128 * 128) * 4)

__global__ __launch_bounds__(256) void node_proj_kernel(
    const float* __restrict__ nf, const float* __restrict__ W1)
{
    extern __shared__ float s1[];
    float* As = s1;              // [64][128]  node features
    float* Bs = s1 + 64 * 128;   // [128][128] weight tile

    const int n0  = blockIdx.x * 64;
    const int j0  = blockIdx.y * 128;   // global P column tile: 0,128,256,384
    const int tid = threadIdx.x;

    // Load A tile (coalesced float4), clamp node index for tail block
    for (int t = tid; t < 64 * 32; t += 256) {
        int n = t >> 5, kc = t & 31;
        int ng = n0 + n; if (ng >= N_NODES) ng = N_NODES - 1;
        reinterpret_cast<float4*>(As)[n * 32 + kc] =
            reinterpret_cast<const float4*>(nf)[ng * 32 + kc];
    }
    // Load B tile: cols j0..j0+127 of [W1a | W1b]
    for (int t = tid; t < 128 * 32; t += 256) {
        int k = t >> 5, jc = t & 31;
        const float4* src = (j0 < 256)
            ? reinterpret_cast<const float4*>(W1 + k * 256 + j0) + jc
            : reinterpret_cast<const float4*>(W1 + (128 + k) * 256 + (j0 - 256)) + jc;
        reinterpret_cast<float4*>(Bs)[k * 32 + jc] = *src;
    }
    __syncthreads();

    const int jt = tid & 31;   // 32 col-groups of 4
    const int nt = tid >> 5;   // 8 node-groups of 8
    const int nb = nt * 8;
    const int jb = jt * 4;

    unsigned long long acc[4][4];
#pragma unroll
    for (int i = 0; i < 4; i++)
#pragma unroll
        for (int jj = 0; jj < 4; jj++) acc[i][jj] = 0ull;

#pragma unroll 4
    for (int k = 0; k < 128; k++) {
        float a[8];
#pragma unroll
        for (int i = 0; i < 8; i++) a[i] = As[(nb + i) * 128 + k];   // warp-broadcast
        float4 bv = *reinterpret_cast<const float4*>(Bs + k * 128 + jb);
        unsigned long long bp[4] = { pack2(bv.x, bv.x), pack2(bv.y, bv.y),
                                     pack2(bv.z, bv.z), pack2(bv.w, bv.w) };
#pragma unroll
        for (int i = 0; i < 4; i++) {
            unsigned long long ap = pack2(a[2 * i], a[2 * i + 1]);
            fma2(acc[i][0], ap, bp[0]);
            fma2(acc[i][1], ap, bp[1]);
            fma2(acc[i][2], ap, bp[2]);
            fma2(acc[i][3], ap, bp[3]);
        }
    }

#pragma unroll
    for (int i = 0; i < 4; i++) {
        float2 u0 = unpack2(acc[i][0]), u1 = unpack2(acc[i][1]);
        float2 u2 = unpack2(acc[i][2]), u3 = unpack2(acc[i][3]);
        int nA = n0 + nb + 2 * i;
        if (nA < N_NODES)
            *reinterpret_cast<float4*>(g_P + nA * 512 + j0 + jb) =
                make_float4(u0.x, u1.x, u2.x, u3.x);
        int nB = nA + 1;
        if (nB < N_NODES)
            *reinterpret_cast<float4*>(g_P + nB * 512 + j0 + jb) =
                make_float4(u0.y, u1.y, u2.y, u3.y);
    }
}

// =====================================================================================
// Kernel 2: fused edge MLP.  Per block: 64 edges, 512 threads.
//   stage1: t = ea @ W1c ; h = relu(t + P[row][:256] + P[col][256:] + b1) -> smem H
//   stage2: out = h @ W2 + b2
// smem: W1c 64KB + W2 64KB + Ea 16KB + H 64KB + biases/indices ~= 214.8 KB (1 CTA/SM)
// =====================================================================================
#define K2_W1C   (64 * 256)
#define K2_W2    (256 * 64)
#define K2_EA    (64 * 64)
#define K2_H     (64 * 256)
#define K2_FLOATS (K2_W1C + K2_W2 + K2_EA + K2_H + 256 + 64)
#define K2_SMEM  (K2_FLOATS * 4 + 128 * 4)

__global__ __launch_bounds__(512, 1) void edge_mlp_kernel(
    const int* __restrict__ ei,          // [2][N_EDGES] int32 (JAX x64 disabled -> int32)
    const float* __restrict__ ea,        // [N_EDGES][64]
    const float* __restrict__ W1,        // [320][256]
    const float* __restrict__ b1,        // [256]
    const float* __restrict__ W2,        // [256][64]
    const float* __restrict__ b2,        // [64]
    float* __restrict__ out)             // [N_EDGES][64]
{
    extern __shared__ float s2[];
    float* Ws1 = s2;                      // [64][256]
    float* Ws2 = Ws1 + K2_W1C;            // [256][64]
    float* Ea  = Ws2 + K2_W2;             // [64][64]
    float* Hs  = Ea + K2_EA;              // [64][256]
    float* b1s = Hs + K2_H;               // [256]
    float* b2s = b1s + 256;               // [64]
    int*   rs  = reinterpret_cast<int*>(b2s + 64);  // [64]
    int*   cs  = rs + 64;                 // [64]

    const int tid = threadIdx.x;
    const int e0  = blockIdx.x * 64;

    // ---- load weights (contiguous copies) ----
    for (int t = tid; t < K2_W1C / 4; t += 512)  // W1 rows 256..319 are contiguous
        reinterpret_cast<float4*>(Ws1)[t] =
            reinterpret_cast<const float4*>(W1 + 256 * 256)[t];
    for (int t = tid; t < K2_W2 / 4; t += 512)
        reinterpret_cast<float4*>(Ws2)[t] = reinterpret_cast<const float4*>(W2)[t];
    // ---- edge attr tile (zero-fill past end) ----
    for (int t = tid; t < K2_EA / 4; t += 512) {
        int gi = e0 * 16 + t;
        float4 v = make_float4(0.f, 0.f, 0.f, 0.f);
        if (gi < N_EDGES * 16) v = reinterpret_cast<const float4*>(ea)[gi];
        reinterpret_cast<float4*>(Ea)[t] = v;
    }
    // ---- biases + indices (indices clamped defensively: never OOB) ----
    if (tid < 256) b1s[tid] = b1[tid];
    if (tid >= 256 && tid < 320) b2s[tid - 256] = b2[tid - 256];
    if (tid >= 320 && tid < 384) {
        int e = tid - 320;
        int ge = e0 + e; if (ge >= N_EDGES) ge = N_EDGES - 1;
        int r = ei[ge];
        int c = ei[N_EDGES + ge];
        rs[e] = min(max(r, 0), N_NODES - 1);
        cs[e] = min(max(c, 0), N_NODES - 1);
    }
    __syncthreads();

    // ================= stage 1: t = ea @ W1c =================
    // thread tile: 8 edges x 4 hidden.  jt in [0,64) -> hidden jb=jt*4 ; et in [0,8) -> edges eb=et*8
    const int jt = tid & 63;
    const int et = tid >> 6;
    const int eb = et * 8;
    const int jb = jt * 4;

    unsigned long long acc1[4][4];
#pragma unroll
    for (int i = 0; i < 4; i++)
#pragma unroll
        for (int jj = 0; jj < 4; jj++) acc1[i][jj] = 0ull;

#pragma unroll 4
    for (int k = 0; k < 64; k++) {
        float a[8];
#pragma unroll
        for (int i = 0; i < 8; i++) a[i] = Ea[(eb + i) * 64 + k];   // warp-broadcast
        float4 bv = *reinterpret_cast<const float4*>(Ws1 + k * 256 + jb);
        unsigned long long bp[4] = { pack2(bv.x, bv.x), pack2(bv.y, bv.y),
                                     pack2(bv.z, bv.z), pack2(bv.w, bv.w) };
#pragma unroll
        for (int i = 0; i < 4; i++) {
            unsigned long long ap = pack2(a[2 * i], a[2 * i + 1]);
            fma2(acc1[i][0], ap, bp[0]);
            fma2(acc1[i][1], ap, bp[1]);
            fma2(acc1[i][2], ap, bp[2]);
            fma2(acc1[i][3], ap, bp[3]);
        }
    }

    // epilogue: add gathered node projections (L2-resident) + b1, relu, write H tile
    {
        const float4 bb = *reinterpret_cast<const float4*>(b1s + jb);
#pragma unroll
        for (int i = 0; i < 4; i++) {
            float2 u0 = unpack2(acc1[i][0]), u1 = unpack2(acc1[i][1]);
            float2 u2 = unpack2(acc1[i][2]), u3 = unpack2(acc1[i][3]);
#pragma unroll
            for (int half = 0; half < 2; half++) {
                int el = eb + 2 * i + half;
                float4 pa = *reinterpret_cast<const float4*>(g_P + (size_t)rs[el] * 512 + jb);
                float4 pb = *reinterpret_cast<const float4*>(g_P + (size_t)cs[el] * 512 + 256 + jb);
                float v0 = (half ? u0.y : u0.x) + pa.x + pb.x + bb.x;
                float v1 = (half ? u1.y : u1.x) + pa.y + pb.y + bb.y;
                float v2 = (half ? u2.y : u2.x) + pa.z + pb.z + bb.z;
                float v3 = (half ? u3.y : u3.x) + pa.w + pb.w + bb.w;
                *reinterpret_cast<float4*>(Hs + el * 256 + jb) =
                    make_float4(fmaxf(v0, 0.f), fmaxf(v1, 0.f),
                                fmaxf(v2, 0.f), fmaxf(v3, 0.f));
            }
        }
    }
    __syncthreads();

    // ================= stage 2: out = h @ W2 + b2 =================
    // thread tile: 2 edges x 4 out-cols, accumulators packed in col-pairs (native LDS.64 on W2)
    const int jt2 = tid & 15;
    const int et2 = tid >> 4;       // 0..31
    const int el0 = et2 * 2;
    const int j2  = jt2 * 4;

    unsigned long long acc2[2][2] = { {0ull, 0ull}, {0ull, 0ull} };

#pragma unroll 8
    for (int k = 0; k < 256; k++) {
        float a0 = Hs[el0 * 256 + k];
        float a1 = Hs[(el0 + 1) * 256 + k];
        unsigned long long ap0 = pack2(a0, a0);
        unsigned long long ap1 = pack2(a1, a1);
        unsigned long long bv0 = *reinterpret_cast<const unsigned long long*>(Ws2 + k * 64 + j2);
        unsigned long long bv1 = *reinterpret_cast<const unsigned long long*>(Ws2 + k * 64 + j2 + 2);
        fma2(acc2[0][0], ap0, bv0);
        fma2(acc2[0][1], ap0, bv1);
        fma2(acc2[1][0], ap1, bv0);
        fma2(acc2[1][1], ap1, bv1);
    }

    const float2 c0 = *reinterpret_cast<const float2*>(b2s + j2);
    const float2 c1 = *reinterpret_cast<const float2*>(b2s + j2 + 2);
#pragma unroll
    for (int e = 0; e < 2; e++) {
        int ge = e0 + el0 + e;
        if (ge < N_EDGES) {
            float2 v0 = unpack2(acc2[e][0]);
            float2 v1 = unpack2(acc2[e][1]);
            *reinterpret_cast<float4*>(out + (size_t)ge * 64 + j2) =
                make_float4(v0.x + c0.x, v0.y + c0.y, v1.x + c1.x, v1.y + c1.y);
        }
    }
}

// =====================================================================================
extern "C" void kernel_launch(void* const* d_in, const int* in_sizes, int n_in,
                              void* d_out, int out_size)
{
    const float* node_feats = (const float*)d_in[0];
    const int*   edge_index = (const int*)d_in[1];    // int32 (JAX default, x64 disabled)
    const float* edge_attr  = (const float*)d_in[2];
    const float* W1         = (const float*)d_in[3];
    const float* b1         = (const float*)d_in[4];
    const float* W2         = (const float*)d_in[5];
    const float* b2         = (const float*)d_in[6];
    float*       out        = (float*)d_out;

    cudaFuncSetAttribute(node_proj_kernel,
                         cudaFuncAttributeMaxDynamicSharedMemorySize, K1_SMEM);
    cudaFuncSetAttribute(edge_mlp_kernel,
                         cudaFuncAttributeMaxDynamicSharedMemorySize, K2_SMEM);

    dim3 g1((N_NODES + 63) / 64, 4);
    node_proj_kernel<<<g1, 256, K1_SMEM>>>(node_feats, W1);

    int g2 = (N_EDGES + 63) / 64;
    edge_mlp_kernel<<<g2, 512, K2_SMEM>>>(edge_index, edge_attr, W1, b1, W2, b2, out);
}

// round 7
// speedup vs baseline: 1.0698x; 1.0698x over previous
#include <cuda_runtime.h>
#include <cstdint>

#define N_NODES 50000
#define N_EDGES 500000

typedef unsigned long long u64;

// Scratch: P[n][0:256] = nf[n] @ W1[0:128,:],  P[n][256:512] = nf[n] @ W1[128:256,:]
__device__ float g_P[(size_t)N_NODES * 512];

// ---------------- packed f32x2 helpers (exact fp32, 2x FMA throughput) ----------------
__device__ __forceinline__ u64 pack2(float lo, float hi) {
    u64 r;
    asm("mov.b64 %0, {%1, %2};" : "=l"(r) : "r"(__float_as_uint(lo)), "r"(__float_as_uint(hi)));
    return r;
}
__device__ __forceinline__ void fma2(u64& acc, u64 a, u64 b) {
    asm("fma.rn.f32x2 %0, %1, %2, %0;" : "+l"(acc) : "l"(a), "l"(b));
}
__device__ __forceinline__ u64 add2(u64 a, u64 b) {
    u64 r;
    asm("add.rn.f32x2 %0, %1, %2;" : "=l"(r) : "l"(a), "l"(b));
    return r;
}
__device__ __forceinline__ float2 unpack2(u64 v) {
    unsigned int lo, hi;
    asm("mov.b64 {%0, %1}, %2;" : "=r"(lo), "=r"(hi) : "l"(v));
    return make_float2(__uint_as_float(lo), __uint_as_float(hi));
}

// =====================================================================================
// Kernel 1: node projection  P = nf @ [W1a | W1b]   (M=50000, K=128, Ncols=512)
// 64 nodes x 128 cols per block, 256 threads, smem 96KB -> 2 CTAs/SM.
// Thread tile: 8 nodes x 4 stride-32 cols.  B reads: scalar LDS, bank=lane (conflict-free).
// =====================================================================================
#define NK_SMEM ((64 * 128 + 128 * 128) * 4)

__global__ __launch_bounds__(256, 2) void node_proj_kernel(
    const float* __restrict__ nf, const float* __restrict__ W1)
{
    extern __shared__ float s1[];
    float* As = s1;              // [64][128]
    float* Bs = s1 + 64 * 128;   // [128][128]

    const int n0  = blockIdx.x * 64;
    const int j0  = blockIdx.y * 128;
    const int tid = threadIdx.x;

    for (int t = tid; t < 64 * 32; t += 256) {
        int n = t >> 5, kc = t & 31;
        int ng = min(n0 + n, N_NODES - 1);
        reinterpret_cast<float4*>(As)[t] =
            reinterpret_cast<const float4*>(nf)[ng * 32 + kc];
    }
    {
        const float* src = (j0 < 256) ? (W1 + j0) : (W1 + 128 * 256 + (j0 - 256));
        for (int t = tid; t < 128 * 32; t += 256) {
            int k = t >> 5, jc = t & 31;
            reinterpret_cast<float4*>(Bs)[t] =
                reinterpret_cast<const float4*>(src + k * 256)[jc];
        }
    }
    __syncthreads();

    const int cg = tid & 31;          // col lane: owns cols {cg + 32j}
    const int eg = tid >> 5;          // 8 node-groups of 8
    const int nb = eg * 8;

    u64 acc[4][4];
#pragma unroll
    for (int ep = 0; ep < 4; ep++)
#pragma unroll
        for (int j = 0; j < 4; j++) acc[ep][j] = 0ull;

#pragma unroll 2
    for (int kb = 0; kb < 128; kb += 4) {
        float av[8][4];
#pragma unroll
        for (int e = 0; e < 8; e++)
            *reinterpret_cast<float4*>(av[e]) =
                *reinterpret_cast<const float4*>(As + (nb + e) * 128 + kb);
#pragma unroll
        for (int t4 = 0; t4 < 4; t4++) {
            u64 bp[4];
#pragma unroll
            for (int j = 0; j < 4; j++) {
                float b = Bs[(kb + t4) * 128 + cg + 32 * j];
                bp[j] = pack2(b, b);
            }
#pragma unroll
            for (int ep = 0; ep < 4; ep++) {
                u64 ap = pack2(av[2 * ep][t4], av[2 * ep + 1][t4]);
#pragma unroll
                for (int j = 0; j < 4; j++) fma2(acc[ep][j], ap, bp[j]);
            }
        }
    }

#pragma unroll
    for (int ep = 0; ep < 4; ep++) {
        int nA = n0 + nb + 2 * ep, nB = nA + 1;
#pragma unroll
        for (int j = 0; j < 4; j++) {
            float2 v = unpack2(acc[ep][j]);
            int c = j0 + cg + 32 * j;
            if (nA < N_NODES) g_P[(size_t)nA * 512 + c] = v.x;
            if (nB < N_NODES) g_P[(size_t)nB * 512 + c] = v.y;
        }
    }
}

// =====================================================================================
// Kernel 2: fused edge MLP.  128 edges/block, 512 threads, smem = 232448B (exact cap).
// Stage 1: 8 edges x 8 stride-32 hidden cols per thread, 2 j-passes (regs), fma-bound.
// Stage 2: 8 edges x 8 stride-8 out cols, 4-way k-split + shfl reduce; W2 at stride 65
//          so scalar B reads are conflict-free (bank = k + col covers all 32 banks).
// smem float offsets:
//   [0,16640)      W1c [64][256] (phase A) / W2s [256][65] (phase B)
//   [16384,24576)  Ea [128][64]   (phase A only)
//   [16640,24832)  Os [128][64]   (phase B only; disjoint from W2s & H)
//   [24832,57600)  H  [128][256]
//   [57600,57856)  b1s ; [57856,57984) rs ; [57984,58112) cs
// =====================================================================================
#define EK_SMEM (58112 * 4)

__global__ __launch_bounds__(512, 1) void edge_mlp_kernel(
    const int* __restrict__ ei,
    const float* __restrict__ ea,
    const float* __restrict__ W1,
    const float* __restrict__ b1,
    const float* __restrict__ W2,
    const float* __restrict__ b2,
    float* __restrict__ out)
{
    extern __shared__ float s2[];
    float* Ws  = s2;            // W1c (phase A) / W2s stride-65 (phase B)
    float* Ea  = s2 + 16384;    // [128][64]
    float* Os  = s2 + 16640;    // [128][64]
    float* Hs  = s2 + 24832;    // [128][256]
    float* b1s = s2 + 57600;
    int*   rs  = reinterpret_cast<int*>(s2 + 57856);
    int*   cs  = reinterpret_cast<int*>(s2 + 57984);

    const int tid = threadIdx.x;
    const int e0  = blockIdx.x * 128;

    // ---- phase A loads ----
    for (int t = tid; t < 4096; t += 512)        // W1c rows 256..319 (contiguous)
        reinterpret_cast<float4*>(Ws)[t] =
            reinterpret_cast<const float4*>(W1 + 256 * 256)[t];
    for (int t = tid; t < 2048; t += 512) {      // Ea tile, zero-fill tail
        int gi = e0 * 16 + t;
        reinterpret_cast<float4*>(Ea)[t] = (gi < N_EDGES * 16)
            ? reinterpret_cast<const float4*>(ea)[gi] : make_float4(0.f, 0.f, 0.f, 0.f);
    }
    if (tid < 256) b1s[tid] = b1[tid];
    if (tid >= 256 && tid < 384) {
        int e  = tid - 256;
        int ge = min(e0 + e, N_EDGES - 1);
        rs[e] = min(max(ei[ge], 0), N_NODES - 1);
        cs[e] = min(max(ei[N_EDGES + ge], 0), N_NODES - 1);
    }
    __syncthreads();

    const int cg = tid & 31;
    const int eg = tid >> 5;
    const int eb = eg * 8;

    // ================= stage 1: h = relu(ea@W1c + P[row] + P[col] + b1) =================
#pragma unroll 1
    for (int pass = 0; pass < 2; pass++) {
        const int jb = pass * 4;                 // cols: cg + 32*(jb+j)
        u64 acc[4][4];
#pragma unroll
        for (int ep = 0; ep < 4; ep++)
#pragma unroll
            for (int j = 0; j < 4; j++) acc[ep][j] = 0ull;

#pragma unroll 2
        for (int kb = 0; kb < 64; kb += 4) {
            float av[8][4];
#pragma unroll
            for (int e = 0; e < 8; e++)
                *reinterpret_cast<float4*>(av[e]) =
                    *reinterpret_cast<const float4*>(Ea + (eb + e) * 64 + kb);
#pragma unroll
            for (int t4 = 0; t4 < 4; t4++) {
                u64 bp[4];
#pragma unroll
                for (int j = 0; j < 4; j++) {
                    float b = Ws[(kb + t4) * 256 + cg + 32 * (jb + j)];
                    bp[j] = pack2(b, b);
                }
#pragma unroll
                for (int ep = 0; ep < 4; ep++) {
                    u64 ap = pack2(av[2 * ep][t4], av[2 * ep + 1][t4]);
#pragma unroll
                    for (int j = 0; j < 4; j++) fma2(acc[ep][j], ap, bp[j]);
                }
            }
        }

        // epilogue: gather P (L2-resident, lanes coalesce to 128B), +b1, relu -> H
        float bb[4];
#pragma unroll
        for (int j = 0; j < 4; j++) bb[j] = b1s[cg + 32 * (jb + j)];
#pragma unroll
        for (int ep = 0; ep < 4; ep++) {
            int ia = eb + 2 * ep, ib = ia + 1;
            const float* p0 = g_P + (size_t)rs[ia] * 512;
            const float* q0 = g_P + (size_t)cs[ia] * 512 + 256;
            const float* p1 = g_P + (size_t)rs[ib] * 512;
            const float* q1 = g_P + (size_t)cs[ib] * 512 + 256;
            float g0[4], g1[4];
#pragma unroll
            for (int j = 0; j < 4; j++) {
                int c = cg + 32 * (jb + j);
                g0[j] = __ldg(p0 + c) + __ldg(q0 + c);
                g1[j] = __ldg(p1 + c) + __ldg(q1 + c);
            }
#pragma unroll
            for (int j = 0; j < 4; j++) {
                float2 v = unpack2(acc[ep][j]);
                int c = cg + 32 * (jb + j);
                Hs[ia * 256 + c] = fmaxf(v.x + g0[j] + bb[j], 0.f);
                Hs[ib * 256 + c] = fmaxf(v.y + g1[j] + bb[j], 0.f);
            }
        }
    }
    __syncthreads();   // W1c dead, H complete

    // ---- phase B: stage W2 at row stride 65 (bank = k + col -> conflict-free) ----
    for (int t = tid; t < 16384; t += 512) {
        int k = t >> 6, c = t & 63;
        Ws[k * 65 + c] = W2[t];
    }
    __syncthreads();

    // ================= stage 2: out = h @ W2 + b2 =================
    const int cg2 = tid & 7;                     // cols {cg2 + 8j}
    const int ks  = (tid >> 3) & 3;              // 4-way k-split: k = 8*ks + 32*m + t
#pragma unroll 1
    for (int pass = 0; pass < 2; pass++) {
        const int jb = pass * 4;
        u64 acc[4][4];
#pragma unroll
        for (int ep = 0; ep < 4; ep++)
#pragma unroll
            for (int j = 0; j < 4; j++) acc[ep][j] = 0ull;

#pragma unroll 2
        for (int m = 0; m < 8; m++) {
            const int kb = 8 * ks + 32 * m;
#pragma unroll
            for (int half = 0; half < 2; half++) {
                float av[8][4];
#pragma unroll
                for (int e = 0; e < 8; e++)
                    *reinterpret_cast<float4*>(av[e]) =
                        *reinterpret_cast<const float4*>(Hs + (eb + e) * 256 + kb + 4 * half);
#pragma unroll
                for (int t4 = 0; t4 < 4; t4++) {
                    int k = kb + 4 * half + t4;
                    u64 bp[4];
#pragma unroll
                    for (int j = 0; j < 4; j++) {
                        float b = Ws[k * 65 + cg2 + 8 * (jb + j)];
                        bp[j] = pack2(b, b);
                    }
#pragma unroll
                    for (int ep = 0; ep < 4; ep++) {
                        u64 ap = pack2(av[2 * ep][t4], av[2 * ep + 1][t4]);
#pragma unroll
                        for (int j = 0; j < 4; j++) fma2(acc[ep][j], ap, bp[j]);
                    }
                }
            }
        }
        // reduce the 4 k-split partials (lanes ks=0..3 share cg2): shfl down 8, 16
#pragma unroll
        for (int ep = 0; ep < 4; ep++)
#pragma unroll
            for (int j = 0; j < 4; j++) {
                u64 v = acc[ep][j];
                v = add2(v, __shfl_down_sync(0xffffffffu, v, 8));
                v = add2(v, __shfl_down_sync(0xffffffffu, v, 16));
                acc[ep][j] = v;
            }
        if (ks == 0) {
#pragma unroll
            for (int ep = 0; ep < 4; ep++) {
#pragma unroll
                for (int j = 0; j < 4; j++) {
                    float2 v = unpack2(acc[ep][j]);
                    int c = cg2 + 8 * (jb + j);
                    float bv = __ldg(b2 + c);
                    Os[(eb + 2 * ep) * 64 + c]     = v.x + bv;
                    Os[(eb + 2 * ep + 1) * 64 + c] = v.y + bv;
                }
            }
        }
    }
    __syncthreads();

    // coalesced float4 store Os -> out
    for (int t = tid; t < 2048; t += 512) {
        int gi = e0 * 16 + t;
        if (gi < N_EDGES * 16)
            reinterpret_cast<float4*>(out)[gi] = reinterpret_cast<float4*>(Os)[t];
    }
}

// =====================================================================================
extern "C" void kernel_launch(void* const* d_in, const int* in_sizes, int n_in,
                              void* d_out, int out_size)
{
    const float* node_feats = (const float*)d_in[0];
    const int*   edge_index = (const int*)d_in[1];    // int32 (JAX default, x64 disabled)
    const float* edge_attr  = (const float*)d_in[2];
    const float* W1         = (const float*)d_in[3];
    const float* b1         = (const float*)d_in[4];
    const float* W2         = (const float*)d_in[5];
    const float* b2         = (const float*)d_in[6];
    float*       out        = (float*)d_out;

    cudaFuncSetAttribute(node_proj_kernel,
                         cudaFuncAttributeMaxDynamicSharedMemorySize, NK_SMEM);
    cudaFuncSetAttribute(edge_mlp_kernel,
                         cudaFuncAttributeMaxDynamicSharedMemorySize, EK_SMEM);

    dim3 g1((N_NODES + 63) / 64, 4);
    node_proj_kernel<<<g1, 256, NK_SMEM>>>(node_feats, W1);

    int g2 = (N_EDGES + 127) / 128;
    edge_mlp_kernel<<<g2, 512, EK_SMEM>>>(edge_index, edge_attr, W1, b1, W2, b2, out);
}

// round 8
// speedup vs baseline: 1.1736x; 1.0970x over previous
#include <cuda_runtime.h>
#include <cstdint>

#define N_NODES 50000
#define N_EDGES 500000

typedef unsigned long long u64;

// Scratch: P[n][0:256] = nf[n] @ W1[0:128,:],  P[n][256:512] = nf[n] @ W1[128:256,:]
__device__ float g_P[(size_t)N_NODES * 512];

// ---------------- packed f32x2 helpers (exact fp32) ----------------
__device__ __forceinline__ u64 pack2(float lo, float hi) {
    u64 r;
    asm("mov.b64 %0, {%1, %2};" : "=l"(r) : "r"(__float_as_uint(lo)), "r"(__float_as_uint(hi)));
    return r;
}
__device__ __forceinline__ void fma2(u64& acc, u64 a, u64 b) {
    asm("fma.rn.f32x2 %0, %1, %2, %0;" : "+l"(acc) : "l"(a), "l"(b));
}
__device__ __forceinline__ u64 add2(u64 a, u64 b) {
    u64 r;
    asm("add.rn.f32x2 %0, %1, %2;" : "=l"(r) : "l"(a), "l"(b));
    return r;
}
__device__ __forceinline__ float2 unpack2(u64 v) {
    unsigned int lo, hi;
    asm("mov.b64 {%0, %1}, %2;" : "=r"(lo), "=r"(hi) : "l"(v));
    return make_float2(__uint_as_float(lo), __uint_as_float(hi));
}
__device__ __forceinline__ u64 lds_u64(const float* p) {
    return *reinterpret_cast<const u64*>(p);
}

// =====================================================================================
// Kernel 1: node projection  P = nf @ [W1a | W1b]
// 64 nodes x 128 cols / block, 256 threads. k-pair packed: A broadcast LDS.64 from
// row-major As; B LDS.64 pairs from k-minor Bt (stride 130 -> conflict-free).
// smem = (8192 + 128*130)*4 = 99328 B -> 2 CTAs/SM.
// =====================================================================================
#define NK_SMEM ((64 * 128 + 128 * 130) * 4)

__global__ __launch_bounds__(256, 2) void node_proj_kernel(
    const float* __restrict__ nf, const float* __restrict__ W1)
{
    extern __shared__ float s1[];
    float* As = s1;              // [64][128] row-major
    float* Bt = s1 + 64 * 128;   // [128 c][stride 130] k-pairs

    const int n0  = blockIdx.x * 64;
    const int j0  = blockIdx.y * 128;
    const int tid = threadIdx.x;

    for (int t = tid; t < 64 * 32; t += 256) {
        int n = t >> 5, kc = t & 31;
        int ng = min(n0 + n, N_NODES - 1);
        reinterpret_cast<float4*>(As)[t] =
            reinterpret_cast<const float4*>(nf)[ng * 32 + kc];
    }
    {
        const float* src = (j0 < 256) ? (W1 + j0) : (W1 + 128 * 256 + (j0 - 256));
        for (int t = tid; t < 128 * 64; t += 256) {   // c = t&127, kp = t>>7
            int c = t & 127, kp = t >> 7;
            float w0 = src[(2 * kp) * 256 + c];
            float w1 = src[(2 * kp + 1) * 256 + c];
            *reinterpret_cast<u64*>(Bt + c * 130 + 2 * kp) = pack2(w0, w1);
        }
    }
    __syncthreads();

    const int cg = tid & 31;
    const int eg = tid >> 5;
    const int nb = eg * 8;

    u64 acc[8][4];
#pragma unroll
    for (int n = 0; n < 8; n++)
#pragma unroll
        for (int j = 0; j < 4; j++) acc[n][j] = 0ull;

#pragma unroll 4
    for (int kp = 0; kp < 64; kp++) {
        u64 av[8];
#pragma unroll
        for (int n = 0; n < 8; n++)
            av[n] = lds_u64(As + (nb + n) * 128 + 2 * kp);   // warp-broadcast
#pragma unroll
        for (int j = 0; j < 4; j++) {
            u64 bv = lds_u64(Bt + (cg + 32 * j) * 130 + 2 * kp);
#pragma unroll
            for (int n = 0; n < 8; n++) fma2(acc[n][j], av[n], bv);
        }
    }

#pragma unroll
    for (int n = 0; n < 8; n++) {
        int ng = n0 + nb + n;
        if (ng < N_NODES) {
#pragma unroll
            for (int j = 0; j < 4; j++) {
                float2 v = unpack2(acc[n][j]);
                g_P[(size_t)ng * 512 + j0 + cg + 32 * j] = v.x + v.y;
            }
        }
    }
}

// =====================================================================================
// Kernel 2: fused edge MLP.  128 edges/block, 512 threads, smem = 232448B (cap), 1 CTA/SM.
// k-pair packed FFMA2 in both stages: zero operand MOVs.
// smem float offsets:
//   [0,16896)      Wt1 [256 c][stride 66]  (phase A) / Wt2 [64 o][stride 258] (phase B)
//   [16896,25088)  Ea [128][64] row-major (phase A) / Os [128][64] (phase B)
//   [25088,57856)  H  [128][256] row-major
//   [57856,57984)  rs ; [57984,58112) cs
// =====================================================================================
#define EK_SMEM (58112 * 4)

__global__ __launch_bounds__(512, 1) void edge_mlp_kernel(
    const int* __restrict__ ei,
    const float* __restrict__ ea,
    const float* __restrict__ W1,
    const float* __restrict__ b1,
    const float* __restrict__ W2,
    const float* __restrict__ b2,
    float* __restrict__ out)
{
    extern __shared__ float s2[];
    float* Wf  = s2;            // Wt1 (phase A) / Wt2 (phase B)
    float* Ea  = s2 + 16896;    // [128][64] ; reused as Os
    float* Hs  = s2 + 25088;    // [128][256]
    int*   rs  = reinterpret_cast<int*>(s2 + 57856);
    int*   cs  = reinterpret_cast<int*>(s2 + 57984);

    const int tid = threadIdx.x;
    const int e0  = blockIdx.x * 128;

    // ---- phase A fills ----
    for (int t = tid; t < 256 * 32; t += 512) {   // Wt1: c = t&255, kp = t>>8
        int c = t & 255, kp = t >> 8;
        float w0 = W1[(256 + 2 * kp) * 256 + c];
        float w1 = W1[(256 + 2 * kp + 1) * 256 + c];
        *reinterpret_cast<u64*>(Wf + c * 66 + 2 * kp) = pack2(w0, w1);
    }
    for (int t = tid; t < 2048; t += 512) {       // Ea tile, zero-fill tail
        int gi = e0 * 16 + t;
        reinterpret_cast<float4*>(Ea)[t] = (gi < N_EDGES * 16)
            ? reinterpret_cast<const float4*>(ea)[gi] : make_float4(0.f, 0.f, 0.f, 0.f);
    }
    if (tid < 128) {
        int ge = min(e0 + tid, N_EDGES - 1);
        rs[tid] = min(max(ei[ge], 0), N_NODES - 1);
    } else if (tid < 256) {
        int e = tid - 128;
        int ge = min(e0 + e, N_EDGES - 1);
        cs[e] = min(max(ei[N_EDGES + ge], 0), N_NODES - 1);
    }
    __syncthreads();

    const int cg = tid & 31;
    const int eg = tid >> 5;
    const int eb = eg * 8;

    // ================= stage 1: h = relu(ea@W1c + P[row] + P[col] + b1) =================
#pragma unroll 1
    for (int pass = 0; pass < 2; pass++) {
        const int jb = pass * 4;                  // cols: cg + 32*(jb+j)
        u64 acc[8][4];
#pragma unroll
        for (int e = 0; e < 8; e++)
#pragma unroll
            for (int j = 0; j < 4; j++) acc[e][j] = 0ull;

#pragma unroll 4
        for (int kp = 0; kp < 32; kp++) {
            u64 av[8];
#pragma unroll
            for (int e = 0; e < 8; e++)
                av[e] = lds_u64(Ea + (eb + e) * 64 + 2 * kp);   // warp-broadcast
#pragma unroll
            for (int j = 0; j < 4; j++) {
                u64 bv = lds_u64(Wf + (cg + 32 * (jb + j)) * 66 + 2 * kp);
#pragma unroll
                for (int e = 0; e < 8; e++) fma2(acc[e][j], av[e], bv);
            }
        }

        // epilogue: k-halves sum + gathered P (L2) + b1, relu -> H (row-major)
        float bb[4];
#pragma unroll
        for (int j = 0; j < 4; j++) bb[j] = __ldg(b1 + cg + 32 * (jb + j));
#pragma unroll
        for (int e = 0; e < 8; e++) {
            int el = eb + e;
            const float* p = g_P + (size_t)rs[el] * 512;
            const float* q = g_P + (size_t)cs[el] * 512 + 256;
#pragma unroll
            for (int j = 0; j < 4; j++) {
                int c = cg + 32 * (jb + j);
                float2 v = unpack2(acc[e][j]);
                float h = v.x + v.y + __ldg(p + c) + __ldg(q + c) + bb[j];
                Hs[el * 256 + c] = fmaxf(h, 0.f);
            }
        }
    }
    __syncthreads();   // Wt1 dead, H complete

    // ---- phase B: Wt2 [64 o][stride 258] k-pairs ----
    for (int t = tid; t < 64 * 128; t += 512) {   // o = t&63, kp = t>>6
        int o = t & 63, kp = t >> 6;
        float w0 = W2[(2 * kp) * 64 + o];
        float w1 = W2[(2 * kp + 1) * 64 + o];
        *reinterpret_cast<u64*>(Wf + o * 258 + 2 * kp) = pack2(w0, w1);
    }
    __syncthreads();

    // ================= stage 2: out = h @ W2 + b2 =================
    const int ks  = tid & 3;                      // 4-way k-split
    const int og  = (tid >> 2) & 7;               // out col group
    float* Os = Ea;                               // reuse (Ea dead)

#pragma unroll 1
    for (int pass = 0; pass < 2; pass++) {
        const int jb = pass * 4;                  // o = og + 8*(jb+j)
        u64 acc[8][4];
#pragma unroll
        for (int e = 0; e < 8; e++)
#pragma unroll
            for (int j = 0; j < 4; j++) acc[e][j] = 0ull;

#pragma unroll 2
        for (int m = 0; m < 8; m++) {
#pragma unroll
            for (int t4 = 0; t4 < 4; t4++) {
                int kb = 8 * ks + 32 * m + 2 * t4;
                u64 av[8];
#pragma unroll
                for (int e = 0; e < 8; e++)
                    av[e] = lds_u64(Hs + (eb + e) * 256 + kb);
#pragma unroll
                for (int j = 0; j < 4; j++) {
                    u64 bv = lds_u64(Wf + (og + 8 * (jb + j)) * 258 + kb);
#pragma unroll
                    for (int e = 0; e < 8; e++) fma2(acc[e][j], av[e], bv);
                }
            }
        }
        // reduce across ks (lanes +1, +2), then k-halves sum + b2
#pragma unroll
        for (int e = 0; e < 8; e++)
#pragma unroll
            for (int j = 0; j < 4; j++) {
                u64 v = acc[e][j];
                v = add2(v, __shfl_down_sync(0xffffffffu, v, 1));
                v = add2(v, __shfl_down_sync(0xffffffffu, v, 2));
                acc[e][j] = v;
            }
        if (ks == 0) {
#pragma unroll
            for (int e = 0; e < 8; e++)
#pragma unroll
                for (int j = 0; j < 4; j++) {
                    int o = og + 8 * (jb + j);
                    float2 v = unpack2(acc[e][j]);
                    Os[(eb + e) * 64 + o] = v.x + v.y + __ldg(b2 + o);
                }
        }
    }
    __syncthreads();

    // coalesced float4 store Os -> out
    for (int t = tid; t < 2048; t += 512) {
        int gi = e0 * 16 + t;
        if (gi < N_EDGES * 16)
            reinterpret_cast<float4*>(out)[gi] = reinterpret_cast<float4*>(Os)[t];
    }
}

// =====================================================================================
extern "C" void kernel_launch(void* const* d_in, const int* in_sizes, int n_in,
                              void* d_out, int out_size)
{
    const float* node_feats = (const float*)d_in[0];
    const int*   edge_index = (const int*)d_in[1];    // int32 (JAX default, x64 disabled)
    const float* edge_attr  = (const float*)d_in[2];
    const float* W1         = (const float*)d_in[3];
    const float* b1         = (const float*)d_in[4];
    const float* W2         = (const float*)d_in[5];
    const float* b2         = (const float*)d_in[6];
    float*       out        = (float*)d_out;

    cudaFuncSetAttribute(node_proj_kernel,
                         cudaFuncAttributeMaxDynamicSharedMemorySize, NK_SMEM);
    cudaFuncSetAttribute(edge_mlp_kernel,
                         cudaFuncAttributeMaxDynamicSharedMemorySize, EK_SMEM);

    dim3 g1((N_NODES + 63) / 64, 4);
    node_proj_kernel<<<g1, 256, NK_SMEM>>>(node_feats, W1);

    int g2 = (N_EDGES + 127) / 128;
    edge_mlp_kernel<<<g2, 512, EK_SMEM>>>(edge_index, edge_attr, W1, b1, W2, b2, out);
}